// round 14
// baseline (speedup 1.0000x reference)
#include <cuda_runtime.h>
#include <cuda_fp16.h>
#include <cstdint>

// ---------------------------------------------------------------- constants
#define D       512
#define KCAT3   1536          // [xh, xh, xl] x [eh, el, eh]
#define N_ROWS  16384
#define K_CB    8192
#define BM      128
#define BN      256
#define NT      (K_CB / BN)   // 32
#define NTHR    512
#define CAP     1024
#define MARGIN  0.15f

// ---- pass1 staging: KST=128, 2 buffers, padded row stride 272 B
#define KST1    128
#define NST1    (D / KST1)    // 4 stages per tile
#define P_RS    272
#define P_A     (BM * P_RS)             // 34816
#define P_B     (BN * P_RS)             // 69632
#define P_STAGE (P_A + P_B)             // 104448
#define P_E2S   (2 * P_STAGE)           // 208896
#define P_CV1   (P_E2S + 1024)
#define P_CI1   (P_CV1 + 2048)
#define P_CV2   (P_CI1 + 2048)
#define P_BI    (P_CV2 + 2048)
#define SMEM_P1 (P_BI + 512)            // 216576

// ---- refine staging: KST=64, 4 buffers, padded row stride 144 B
#define KST3    64
#define NST3    (KCAT3 / KST3)  // 24
#define R_RS    144
#define R_A     (BM * R_RS)
#define R_B     (BN * R_RS)
#define R_STAGE (R_A + R_B)             // 55296
#define R_E2S   (4 * R_STAGE)           // 221184
#define R_CV1   (R_E2S + 1024)
#define R_CI1   (R_CV1 + 2048)
#define SMEM_RF (R_CI1 + 2048)          // 225280

// ---------------------------------------------------------------- scratch
__device__ __half g_xh[(size_t)N_ROWS * D];
__device__ __half g_eh[(size_t)K_CB * D];
__device__ __half g_ecat3[(size_t)K_CB * KCAT3];
__device__ __half g_xcat3[(size_t)CAP * KCAT3];
__device__ float  g_e2[K_CB];
__device__ int    g_cnt;
__device__ int    g_rows[CAP];
__device__ unsigned long long g_merge[CAP];

// ---------------------------------------------------------------- helpers
__device__ __forceinline__ void mma16816(float* c, const uint32_t* a, uint32_t b0, uint32_t b1) {
    asm volatile(
        "mma.sync.aligned.m16n8k16.row.col.f32.f16.f16.f32 "
        "{%0,%1,%2,%3}, {%4,%5,%6,%7}, {%8,%9}, {%0,%1,%2,%3};"
        : "+f"(c[0]), "+f"(c[1]), "+f"(c[2]), "+f"(c[3])
        : "r"(a[0]), "r"(a[1]), "r"(a[2]), "r"(a[3]), "r"(b0), "r"(b1));
}
__device__ __forceinline__ void ldmat4(uint32_t& r0, uint32_t& r1, uint32_t& r2, uint32_t& r3,
                                       uint32_t addr) {
    asm volatile("ldmatrix.sync.aligned.m8n8.x4.shared.b16 {%0,%1,%2,%3}, [%4];"
                 : "=r"(r0), "=r"(r1), "=r"(r2), "=r"(r3) : "r"(addr));
}
__device__ __forceinline__ void cp16(uint32_t dst, const void* src) {
    asm volatile("cp.async.cg.shared.global [%0], [%1], 16;" :: "r"(dst), "l"(src));
}
#define CP_COMMIT() asm volatile("cp.async.commit_group;" ::: "memory")
#define CP_WAIT0()  asm volatile("cp.async.wait_group 0;" ::: "memory")
#define CP_WAIT2()  asm volatile("cp.async.wait_group 2;" ::: "memory")
__device__ __forceinline__ uint32_t smem_u32(const void* p) {
    return (uint32_t)__cvta_generic_to_shared(p);
}

// ---------------------------------------------------------------- prep
__global__ void __launch_bounds__(128) init_misc() {
    int i = blockIdx.x * 128 + threadIdx.x;
    if (i < CAP) g_merge[i] = ~0ull;
    if (i == 0) g_cnt = 0;
}

__global__ void __launch_bounds__(256) x_prep(const float* __restrict__ x, int n4) {
    int i = blockIdx.x * 256 + threadIdx.x;
    if (i >= n4) return;
    float4 v = reinterpret_cast<const float4*>(x)[i];
    __half2 p0 = __floats2half2_rn(v.x, v.y);
    __half2 p1 = __floats2half2_rn(v.z, v.w);
    uint2 pk;
    pk.x = *(uint32_t*)&p0;
    pk.y = *(uint32_t*)&p1;
    reinterpret_cast<uint2*>(g_xh)[i] = pk;
}

// warp-per-row: eh, ecat3 (h,l,h) and e2 in one pass
__global__ void __launch_bounds__(256) e_prep(const float* __restrict__ cb) {
    int row  = blockIdx.x * 8 + (threadIdx.x >> 5);
    int lane = threadIdx.x & 31;
    const float4* src = reinterpret_cast<const float4*>(cb + (size_t)row * D);
    __half* eh  = g_eh + (size_t)row * D;
    __half* ec  = g_ecat3 + (size_t)row * KCAT3;
    float s = 0.0f;
    #pragma unroll
    for (int i = 0; i < 4; i++) {
        int q = lane + i * 32;            // float4 index 0..127
        float4 v = src[q];
        s += v.x * v.x + v.y * v.y + v.z * v.z + v.w * v.w;
        int c = q * 4;
        float f[4] = {v.x, v.y, v.z, v.w};
        #pragma unroll
        for (int j = 0; j < 4; j++) {
            __half h = __float2half_rn(f[j]);
            __half l = __float2half_rn(f[j] - __half2float(h));
            eh[c + j]        = h;
            ec[c + j]        = h;
            ec[512 + c + j]  = l;
            ec[1024 + c + j] = h;
        }
    }
    #pragma unroll
    for (int o = 16; o; o >>= 1) s += __shfl_xor_sync(0xffffffffu, s, o);
    if (lane == 0) g_e2[row] = s;
}

__global__ void __launch_bounds__(64) gather_split(const float* __restrict__ x) {
    int slot = blockIdx.x;
    if (slot >= g_cnt || slot >= CAP) return;
    int row = g_rows[slot];
    size_t base = (size_t)slot * KCAT3;
    for (int c = threadIdx.x; c < D; c += 64) {
        float v = x[(size_t)row * D + c];
        __half h = __float2half_rn(v);
        __half l = __float2half_rn(v - __half2float(h));
        g_xcat3[base + c]        = h;
        g_xcat3[base + 512 + c]  = h;
        g_xcat3[base + 1024 + c] = l;
    }
}

// ---------------------------------------------------------------- pass 1
__global__ void __launch_bounds__(NTHR, 1) pass1_kernel(const float* __restrict__ cb,
                                                        float* __restrict__ out) {
    extern __shared__ char sm[];
    const uint32_t smb = smem_u32(sm);
    const int tid  = threadIdx.x;
    const int lane = tid & 31;
    const int wid  = tid >> 5;
    const int wm   = wid >> 2;
    const int wn   = wid & 3;
    const int grp  = lane >> 2;
    const int qid  = lane & 3;
    const int rowBase = blockIdx.x * BM;

    float* e2s = (float*)(sm + P_E2S);
    float* cv1 = (float*)(sm + P_CV1);
    int*   ci1 = (int*)(sm + P_CI1);
    float* cv2 = (float*)(sm + P_CV2);
    int*   bis = (int*)(sm + P_BI);

    float rv1 = 3.4028235e38f, rv2 = 3.4028235e38f;
    int   ri1 = 0;

    const uint32_t aRow = (uint32_t)(wm * 32 + (lane & 15));
    const uint32_t aCol = (uint32_t)((lane >> 4) * 16);
    const uint32_t bRow = (uint32_t)(wn * 64 + (lane >> 4) * 8 + (lane & 7));
    const uint32_t bCol = (uint32_t)(((lane >> 3) & 1) * 16);

    auto issue_stage = [&](int g) {
        const int t = g >> 2;               // /NST1
        const int s = g & 3;
        const int d0 = s * KST1;
        const int cb0 = t * BN;
        uint32_t A = smb + (g & 1) * P_STAGE;
        uint32_t B = A + P_A;
        #pragma unroll
        for (int it = 0; it < 4; it++) {
            int id = tid + it * NTHR;       // 0..2047
            int r = id >> 4, c = id & 15;
            cp16(A + r * P_RS + c * 16, g_xh + (size_t)(rowBase + r) * D + d0 + c * 8);
        }
        #pragma unroll
        for (int it = 0; it < 8; it++) {
            int id = tid + it * NTHR;       // 0..4095
            int r = id >> 4, c = id & 15;
            cp16(B + r * P_RS + c * 16, g_eh + (size_t)(cb0 + r) * D + d0 + c * 8);
        }
        CP_COMMIT();
    };

    issue_stage(0);

    float acc[2][8][4];
    const int S = NT * NST1;                // 128

    for (int g = 0; g < S; g++) {
        const int t = g >> 2;
        const int s = g & 3;

        CP_WAIT0();                         // stage g landed (only outstanding group)
        __syncthreads();                    // visible to all; all done MMA(g-1)
        if (g + 1 < S) issue_stage(g + 1);  // into buf (g+1)&1 (free since MMA(g-1) done)

        if (s == 0) {
            if (tid < BN) e2s[tid] = g_e2[t * BN + tid];
            #pragma unroll
            for (int mi = 0; mi < 2; mi++)
                #pragma unroll
                for (int ni = 0; ni < 8; ni++)
                    #pragma unroll
                    for (int j = 0; j < 4; j++) acc[mi][ni][j] = 0.0f;
        }

        // ---- MMA on buffer g&1 (KST1=128 -> 8 k-steps of 16)
        {
            uint32_t A = smb + (g & 1) * P_STAGE;
            uint32_t B = A + P_A;
            #pragma unroll
            for (int kk = 0; kk < 8; kk++) {
                uint32_t a[2][4];
                #pragma unroll
                for (int mi = 0; mi < 2; mi++)
                    ldmat4(a[mi][0], a[mi][1], a[mi][2], a[mi][3],
                           A + (aRow + mi * 16) * P_RS + kk * 32 + aCol);
                #pragma unroll
                for (int p = 0; p < 4; p++) {
                    uint32_t b0, b1, b2, b3;
                    ldmat4(b0, b1, b2, b3, B + (bRow + p * 16) * P_RS + kk * 32 + bCol);
                    #pragma unroll
                    for (int mi = 0; mi < 2; mi++) {
                        mma16816(acc[mi][2 * p],     a[mi], b0, b1);
                        mma16816(acc[mi][2 * p + 1], a[mi], b2, b3);
                    }
                }
            }
        }

        // ---- per-tile top-2 epilogue
        if (s == NST1 - 1) {
            #pragma unroll
            for (int mi = 0; mi < 2; mi++) {
                #pragma unroll
                for (int h = 0; h < 2; h++) {
                    float v1 = 3.4028235e38f, v2 = 3.4028235e38f;
                    int i1 = 0;
                    #pragma unroll
                    for (int ni = 0; ni < 8; ni++) {
                        #pragma unroll
                        for (int j = 0; j < 2; j++) {
                            int cl = wn * 64 + ni * 8 + qid * 2 + j;
                            float dd = e2s[cl] - 2.0f * acc[mi][ni][h * 2 + j];
                            if (dd < v1) { v2 = v1; v1 = dd; i1 = cl; }
                            else if (dd < v2) v2 = dd;
                        }
                    }
                    #pragma unroll
                    for (int off = 1; off <= 2; off <<= 1) {
                        float w1 = __shfl_xor_sync(0xffffffffu, v1, off);
                        int   j1 = __shfl_xor_sync(0xffffffffu, i1, off);
                        float w2 = __shfl_xor_sync(0xffffffffu, v2, off);
                        if (w1 < v1 || (w1 == v1 && j1 < i1)) {
                            v2 = fminf(v1, w2); v1 = w1; i1 = j1;
                        } else {
                            v2 = fminf(w1, v2);
                        }
                    }
                    if (qid == 0) {
                        int rl = wm * 32 + mi * 16 + grp + h * 8;
                        cv1[wn * 128 + rl] = v1;
                        ci1[wn * 128 + rl] = i1;
                        cv2[wn * 128 + rl] = v2;
                    }
                }
            }
            __syncthreads();
            if (tid < BM) {
                #pragma unroll
                for (int w = 0; w < 4; w++) {
                    float w1 = cv1[w * 128 + tid];
                    int   j1 = t * BN + ci1[w * 128 + tid];
                    float w2 = cv2[w * 128 + tid];
                    if (w1 < rv1 || (w1 == rv1 && j1 < ri1)) {
                        rv2 = fminf(rv1, w2); rv1 = w1; ri1 = j1;
                    } else {
                        rv2 = fminf(w1, rv2);
                    }
                }
            }
            // next write of cv/ci is >= 4 barriers away
        }
    }

    // ---- decide / flag
    if (tid < BM) {
        int b = ri1;
        if (rv2 - rv1 < MARGIN) {
            int pos = atomicAdd(&g_cnt, 1);
            if (pos < CAP) {
                g_rows[pos] = rowBase + tid;
                b = -1;
            }
        }
        bis[tid] = b;
    }
    __syncthreads();

    // ---- gather for decided rows
    const float4* cb4 = reinterpret_cast<const float4*>(cb);
    float4* out4 = reinterpret_cast<float4*>(out);
    for (int i = tid; i < BM * (D / 4); i += NTHR) {
        int r = i >> 7, c = i & 127;
        int idx = bis[r];
        if (idx >= 0)
            out4[(size_t)(rowBase + r) * (D / 4) + c] = cb4[(size_t)idx * (D / 4) + c];
    }
}

// ---------------------------------------------------------------- refine
__global__ void __launch_bounds__(NTHR, 1) refine_kernel() {
    const int rb = blockIdx.x >> 5;       // row block 0..7
    {   // early exit: skip row blocks with no flagged rows
        int cnt = g_cnt; if (cnt > CAP) cnt = CAP;
        if (rb * BM >= cnt) return;
    }
    extern __shared__ char sm[];
    const uint32_t smb = smem_u32(sm);
    const int tid  = threadIdx.x;
    const int lane = tid & 31;
    const int wid  = tid >> 5;
    const int wm   = wid >> 2;
    const int wn   = wid & 3;
    const int grp  = lane >> 2;
    const int qid  = lane & 3;
    const int t    = blockIdx.x & 31;     // col tile
    const int slotBase = rb * BM;
    const int cb0 = t * BN;

    float* e2s = (float*)(sm + R_E2S);
    float* cv1 = (float*)(sm + R_CV1);
    int*   ci1 = (int*)(sm + R_CI1);

    const uint32_t aRow = (uint32_t)(wm * 32 + (lane & 15));
    const uint32_t aCol = (uint32_t)((lane >> 4) * 16);
    const uint32_t bRow = (uint32_t)(wn * 64 + (lane >> 4) * 8 + (lane & 7));
    const uint32_t bCol = (uint32_t)(((lane >> 3) & 1) * 16);

    auto issue_stage = [&](int g) {
        const int d0 = g * KST3;
        uint32_t A = smb + (g & 3) * R_STAGE;
        uint32_t B = A + R_A;
        #pragma unroll
        for (int it = 0; it < 2; it++) {
            int id = tid + it * NTHR;
            int r = id >> 3, c = id & 7;
            cp16(A + r * R_RS + c * 16, g_xcat3 + (size_t)(slotBase + r) * KCAT3 + d0 + c * 8);
        }
        #pragma unroll
        for (int it = 0; it < 4; it++) {
            int id = tid + it * NTHR;
            int r = id >> 3, c = id & 7;
            cp16(B + r * R_RS + c * 16, g_ecat3 + (size_t)(cb0 + r) * KCAT3 + d0 + c * 8);
        }
        CP_COMMIT();
    };

    issue_stage(0); issue_stage(1); issue_stage(2);

    float acc[2][8][4];
    #pragma unroll
    for (int mi = 0; mi < 2; mi++)
        #pragma unroll
        for (int ni = 0; ni < 8; ni++)
            #pragma unroll
            for (int j = 0; j < 4; j++) acc[mi][ni][j] = 0.0f;

    for (int g = 0; g < NST3; g++) {
        CP_WAIT2();
        __syncthreads();
        if (g == 0 && tid < BN) e2s[tid] = g_e2[cb0 + tid];

        uint32_t A = smb + (g & 3) * R_STAGE;
        uint32_t B = A + R_A;
        #pragma unroll
        for (int kk = 0; kk < 4; kk++) {
            uint32_t a[2][4];
            #pragma unroll
            for (int mi = 0; mi < 2; mi++)
                ldmat4(a[mi][0], a[mi][1], a[mi][2], a[mi][3],
                       A + (aRow + mi * 16) * R_RS + kk * 32 + aCol);
            #pragma unroll
            for (int p = 0; p < 4; p++) {
                uint32_t b0, b1, b2, b3;
                ldmat4(b0, b1, b2, b3, B + (bRow + p * 16) * R_RS + kk * 32 + bCol);
                #pragma unroll
                for (int mi = 0; mi < 2; mi++) {
                    mma16816(acc[mi][2 * p],     a[mi], b0, b1);
                    mma16816(acc[mi][2 * p + 1], a[mi], b2, b3);
                }
            }
        }
        if (g + 3 < NST3) issue_stage(g + 3);
    }
    __syncthreads();

    #pragma unroll
    for (int mi = 0; mi < 2; mi++) {
        #pragma unroll
        for (int h = 0; h < 2; h++) {
            float v = 3.4028235e38f;
            int idx = 0;
            #pragma unroll
            for (int ni = 0; ni < 8; ni++) {
                #pragma unroll
                for (int j = 0; j < 2; j++) {
                    int cl = wn * 64 + ni * 8 + qid * 2 + j;
                    float dd = e2s[cl] - 2.0f * acc[mi][ni][h * 2 + j];
                    if (dd < v) { v = dd; idx = cl; }
                }
            }
            #pragma unroll
            for (int off = 1; off <= 2; off <<= 1) {
                float ov = __shfl_xor_sync(0xffffffffu, v, off);
                int   oi = __shfl_xor_sync(0xffffffffu, idx, off);
                if (ov < v || (ov == v && oi < idx)) { v = ov; idx = oi; }
            }
            if (qid == 0) {
                int rl = wm * 32 + mi * 16 + grp + h * 8;
                cv1[wn * 128 + rl] = v;
                ci1[wn * 128 + rl] = idx;
            }
        }
    }
    __syncthreads();
    if (tid < BM) {
        float v = 3.4028235e38f;
        int idx = 0;
        #pragma unroll
        for (int w = 0; w < 4; w++) {
            float ov = cv1[w * 128 + tid];
            int   oi = cb0 + ci1[w * 128 + tid];
            if (ov < v || (ov == v && oi < idx)) { v = ov; idx = oi; }
        }
        uint32_t b = __float_as_uint(v);
        uint32_t key = (b & 0x80000000u) ? ~b : (b | 0x80000000u);
        unsigned long long pk = ((unsigned long long)key << 32) | (uint32_t)idx;
        atomicMin(&g_merge[slotBase + tid], pk);
    }
}

// ---------------------------------------------------------------- scatter
__global__ void __launch_bounds__(128) scatter_kernel(const float* __restrict__ cb,
                                                      float* __restrict__ out) {
    int slot = blockIdx.x;
    int cnt = g_cnt; if (cnt > CAP) cnt = CAP;
    if (slot >= cnt) return;
    int row = g_rows[slot];
    int idx = (int)(uint32_t)(g_merge[slot] & 0xFFFFFFFFull);
    const float4* cb4 = reinterpret_cast<const float4*>(cb);
    float4* out4 = reinterpret_cast<float4*>(out);
    out4[(size_t)row * (D / 4) + threadIdx.x] = cb4[(size_t)idx * (D / 4) + threadIdx.x];
}

// ---------------------------------------------------------------- launch
extern "C" void kernel_launch(void* const* d_in, const int* in_sizes, int n_in,
                              void* d_out, int out_size) {
    const float* x  = (const float*)d_in[0];
    const float* cb = (const float*)d_in[1];
    float* out = (float*)d_out;

    init_misc<<<8, 128>>>();
    x_prep<<<(N_ROWS * D / 4 + 255) / 256, 256>>>(x, N_ROWS * D / 4);
    e_prep<<<K_CB / 8, 256>>>(cb);

    cudaFuncSetAttribute(pass1_kernel, cudaFuncAttributeMaxDynamicSharedMemorySize, SMEM_P1);
    cudaFuncSetAttribute(refine_kernel, cudaFuncAttributeMaxDynamicSharedMemorySize, SMEM_RF);

    pass1_kernel<<<N_ROWS / BM, NTHR, SMEM_P1>>>(cb, out);
    gather_split<<<CAP, 64>>>(x);
    refine_kernel<<<(CAP / BM) * NT, NTHR, SMEM_RF>>>();
    scatter_kernel<<<CAP, 128>>>(cb, out);
}